// round 3
// baseline (speedup 1.0000x reference)
#include <cuda_runtime.h>
#include <cstdint>
#include <cstddef>

#define DI __device__ __forceinline__

#define BATCH 1024
#define NF    32
#define NPAIR 496
#define T_LD  1984
#define X_LD  2048
#define HALFK 31744
#define KTOT  63488
#define H1    1024
#define H2    512

// GEMM tile: BM=128, BN=128, BK=32, 256 threads (8 warps: 2 warp-rows x 4 warp-cols,
// warp tile 64x32). Fragment-order smem with padded s-blocks (1032 floats/block).
#define SBLK 1032
#define ABUF_B (4*SBLK*4)            // 16512 bytes
#define SMEM_DYN (2*(ABUF_B+ABUF_B)) // 66048

__device__ float g_x2[BATCH*X_LD];
__device__ float g_T[2*BATCH*T_LD];
__device__ float g_part0[4*BATCH*H1];
__device__ float g_h0[BATCH*H1];
__device__ float g_part1[4*BATCH*H2];
__device__ float g_h1[BATCH*H2];
__device__ int   g_pi[NPAIR];
__device__ int   g_pj[NPAIR];

DI uint32_t f2tf(float x) {
    uint32_t r;
    asm("cvt.rna.tf32.f32 %0, %1;" : "=r"(r) : "f"(x));
    return r;
}

DI void mma_tf32(float* d, const uint32_t* a, const uint32_t* b) {
    asm volatile(
        "mma.sync.aligned.m16n8k8.row.col.f32.tf32.tf32.f32 "
        "{%0,%1,%2,%3}, {%4,%5,%6,%7}, {%8,%9}, {%0,%1,%2,%3};"
        : "+f"(d[0]), "+f"(d[1]), "+f"(d[2]), "+f"(d[3])
        : "r"(a[0]), "r"(a[1]), "r"(a[2]), "r"(a[3]), "r"(b[0]), "r"(b[1]));
}

// ---------------- small kernels ----------------
__global__ void init_pairs_kernel() {
    if (threadIdx.x == 0) {
        int idx = 0;
        for (int i = 0; i < NF - 1; i++)
            for (int j = i + 1; j < NF; j++) { g_pi[idx] = i; g_pj[idx] = j; idx++; }
    }
}

__global__ void __launch_bounds__(256) se_kernel(const float* __restrict__ x,
                                                 const float* __restrict__ w1,
                                                 const float* __restrict__ w2) {
    __shared__ float xs[X_LD];
    __shared__ float Zs[NF], A1s[4], A2s[NF];
    int b = blockIdx.x, tid = threadIdx.x;
    const float4* xr = (const float4*)(x + (size_t)b * X_LD);
    float4* xs4 = (float4*)xs;
    xs4[tid] = xr[tid];
    xs4[tid + 256] = xr[tid + 256];
    __syncthreads();
    int wid = tid >> 5, lane = tid & 31;
    #pragma unroll
    for (int ff = 0; ff < 4; ff++) {
        int f = wid * 4 + ff;
        float v = xs[f * 64 + lane] + xs[f * 64 + 32 + lane];
        #pragma unroll
        for (int o = 16; o; o >>= 1) v += __shfl_xor_sync(0xffffffffu, v, o);
        if (lane == 0) Zs[f] = v * (1.0f / 64.0f);
    }
    __syncthreads();
    if (tid < 4) {
        float a = 0.f;
        #pragma unroll
        for (int f = 0; f < NF; f++) a += Zs[f] * w1[tid * NF + f];
        A1s[tid] = fmaxf(a, 0.0f);
    }
    __syncthreads();
    if (tid < NF) {
        float a = 0.f;
        #pragma unroll
        for (int r = 0; r < 4; r++) a += A1s[r] * w2[tid * 4 + r];
        A2s[tid] = 1.0f / (1.0f + expf(-a));
    }
    __syncthreads();
    float4* o4 = (float4*)(g_x2 + (size_t)b * X_LD);
    #pragma unroll
    for (int q = 0; q < 2; q++) {
        int i = tid + q * 256;
        float4 v = xs4[i];
        float sc = A2s[i >> 4];
        v.x *= sc; v.y *= sc; v.z *= sc; v.w *= sc;
        o4[i] = v;
    }
}

// t[v][b][i*64+o] = sum_e feats_v[b,i,e] * W_v[i,o,e]
__global__ void __launch_bounds__(256) tfield_kernel(const float* __restrict__ x,
                                                     const float* __restrict__ W1,
                                                     const float* __restrict__ W2) {
    __shared__ float Ws[64 * 68];
    __shared__ float xs[16 * 68];
    __shared__ float ts[1024];
    int v = blockIdx.z, fi = blockIdx.x, b0 = blockIdx.y * 16;
    int tid = threadIdx.x;
    const float* W = (v ? W2 : W1) + (size_t)fi * 4096;
    for (int idx = tid; idx < 4096; idx += 256)
        Ws[(idx >> 6) * 68 + (idx & 63)] = W[idx];
    const float* xsrc = (v ? g_x2 : x) + (size_t)b0 * X_LD + fi * 64;
    for (int idx = tid; idx < 1024; idx += 256)
        xs[(idx >> 6) * 68 + (idx & 63)] = xsrc[(size_t)(idx >> 6) * X_LD + (idx & 63)];
    __syncthreads();
    int o = tid >> 2, bg = tid & 3;
    float s0 = 0.f, s1 = 0.f, s2 = 0.f, s3 = 0.f;
    const float4* wrow = (const float4*)(Ws + o * 68);
    #pragma unroll
    for (int e4 = 0; e4 < 16; e4++) {
        float4 wv = wrow[e4];
        float4 a0 = *(const float4*)(xs + (bg * 4 + 0) * 68 + e4 * 4);
        float4 a1 = *(const float4*)(xs + (bg * 4 + 1) * 68 + e4 * 4);
        float4 a2 = *(const float4*)(xs + (bg * 4 + 2) * 68 + e4 * 4);
        float4 a3 = *(const float4*)(xs + (bg * 4 + 3) * 68 + e4 * 4);
        s0 += wv.x*a0.x + wv.y*a0.y + wv.z*a0.z + wv.w*a0.w;
        s1 += wv.x*a1.x + wv.y*a1.y + wv.z*a1.z + wv.w*a1.w;
        s2 += wv.x*a2.x + wv.y*a2.y + wv.z*a2.z + wv.w*a2.w;
        s3 += wv.x*a3.x + wv.y*a3.y + wv.z*a3.z + wv.w*a3.w;
    }
    ts[(bg * 4 + 0) * 64 + o] = s0;
    ts[(bg * 4 + 1) * 64 + o] = s1;
    ts[(bg * 4 + 2) * 64 + o] = s2;
    ts[(bg * 4 + 3) * 64 + o] = s3;
    __syncthreads();
    float* trow = g_T + (size_t)v * (BATCH * T_LD);
    for (int idx = tid; idx < 1024; idx += 256)
        trow[(size_t)(b0 + (idx >> 6)) * T_LD + fi * 64 + (idx & 63)] = ts[idx];
}

// ---------------- mma.sync tf32 GEMM ----------------
// C[m,n] = sum_k A[m,k] * W[n,k].
// MODE 0: A = on-the-fly bilinear feature tile (fc0), C -> g_part0
// MODE 1: A = g_h0 (fc1), C -> g_part1
//
// smem A (fragment order, per buffer):
//   float index = s*SBLK + (f*32 + lane)*4 + reg   (s: kstep 0..3, f: m16 frag 0..7)
//   reg mapping for element (mr = m&15, kc = k&7): lane=(mr&7)*4+(kc&3), reg=(kc>>2)*2+(mr>>3)
// smem B: float index = s*SBLK + (g*32 + lane)*2 + reg  (g: n8 frag 0..15)
//   element (k, nr=n&7): lane = nr*4 + (kc&3), reg = kc>>2
template<int MODE>
__global__ void __launch_bounds__(256) gemm_kernel(const float* __restrict__ Bw,
                                                   const float* __restrict__ Xin,
                                                   int Ntot, int Ktot, int S) {
    extern __shared__ char smem[];
    int tid = threadIdx.x;
    int w = tid >> 5, l = tid & 31;
    int wr = w >> 2, wc = w & 3;
    int nbn = Ntot >> 7;
    int s  = blockIdx.x % S;
    int nb = (blockIdx.x / S) % nbn;
    int mb = blockIdx.x / (S * nbn);
    int m0 = mb * 128, n0 = nb * 128;
    int Kper = Ktot / S;
    int k_base = s * Kper;
    int ntiles = Kper >> 5;

    float acc[4][4][4];
    #pragma unroll
    for (int i = 0; i < 4; i++)
        #pragma unroll
        for (int j = 0; j < 4; j++)
            #pragma unroll
            for (int q = 0; q < 4; q++) acc[i][j][q] = 0.f;

    // precomputed per-thread writer indices
    // A/B writer: float4 idx4 = tid + it*256 -> r = idx4>>3, c4 = idx4&7
    // element j (k = c4*4+j): ks = c4>>1, kc>>2 = c4&1
    auto sts_a = [&](char* sA, int it, const uint32_t* bits) {
        int idx4 = tid + it * 256;
        int r = idx4 >> 3, c4 = idx4 & 7;
        int ks = c4 >> 1, f = r >> 4, mr = r & 15;
        int reg = (c4 & 1) * 2 + (mr >> 3);
        float* base = (float*)sA + ks * SBLK + (f * 32 + (mr & 7) * 4) * 4 + reg;
        #pragma unroll
        for (int j = 0; j < 4; j++) base[j * 4] = __uint_as_float(bits[j]);
    };
    auto sts_b = [&](char* sB, int it, const uint32_t* bits) {
        int idx4 = tid + it * 256;
        int n = idx4 >> 3, c4 = idx4 & 7;
        int ks = c4 >> 1, g = n >> 3, nr = n & 7;
        int reg = c4 & 1;
        float* base = (float*)sB + ks * SBLK + (g * 32 + nr * 4) * 2 + reg;
        #pragma unroll
        for (int j = 0; j < 4; j++) base[j * 2] = __uint_as_float(bits[j]);
    };

    float4 av[4], bv[4];

    auto load_tile = [&](int kt) {
        int kg = k_base + (kt << 5);
        if (MODE == 0) {
            int half = (kg >= HALFK) ? 1 : 0;
            int rem = kg - half * HALFK;
            int p = rem >> 6, e0 = rem & 63;
            int ip = g_pi[p], jp = g_pj[p];
            const float* tb = g_T + (size_t)half * (BATCH * T_LD) + (size_t)m0 * T_LD + ip * 64 + e0;
            const float* xb = (half ? g_x2 : Xin) + (size_t)m0 * X_LD + jp * 64 + e0;
            #pragma unroll
            for (int it = 0; it < 4; it++) {
                int idx4 = tid + it * 256;
                int r = idx4 >> 3, c4 = idx4 & 7;
                float4 tv = *(const float4*)(tb + (size_t)r * T_LD + c4 * 4);
                float4 xv = *(const float4*)(xb + (size_t)r * X_LD + c4 * 4);
                av[it].x = tv.x * xv.x; av[it].y = tv.y * xv.y;
                av[it].z = tv.z * xv.z; av[it].w = tv.w * xv.w;
            }
        } else {
            const float* ab = g_h0 + (size_t)m0 * Ktot + kg;
            #pragma unroll
            for (int it = 0; it < 4; it++) {
                int idx4 = tid + it * 256;
                int r = idx4 >> 3, c4 = idx4 & 7;
                av[it] = *(const float4*)(ab + (size_t)r * Ktot + c4 * 4);
            }
        }
        const float* bb = Bw + (size_t)n0 * Ktot + kg;
        #pragma unroll
        for (int it = 0; it < 4; it++) {
            int idx4 = tid + it * 256;
            int n = idx4 >> 3, c4 = idx4 & 7;
            bv[it] = *(const float4*)(bb + (size_t)n * Ktot + c4 * 4);
        }
    };
    auto store_tile = [&](int buf) {
        char* sA = smem + buf * (2 * ABUF_B);
        char* sB = sA + ABUF_B;
        #pragma unroll
        for (int it = 0; it < 4; it++) {
            uint32_t bits[4];
            bits[0] = f2tf(av[it].x); bits[1] = f2tf(av[it].y);
            bits[2] = f2tf(av[it].z); bits[3] = f2tf(av[it].w);
            sts_a(sA, it, bits);
        }
        #pragma unroll
        for (int it = 0; it < 4; it++) {
            uint32_t bits[4];
            bits[0] = f2tf(bv[it].x); bits[1] = f2tf(bv[it].y);
            bits[2] = f2tf(bv[it].z); bits[3] = f2tf(bv[it].w);
            sts_b(sB, it, bits);
        }
    };

    load_tile(0);
    store_tile(0);
    __syncthreads();

    for (int kt = 0; kt < ntiles; kt++) {
        int ktn = (kt + 1 < ntiles) ? kt + 1 : kt;
        load_tile(ktn);

        int buf = kt & 1;
        const char* sA = smem + buf * (2 * ABUF_B);
        const char* sB = sA + ABUF_B;
        #pragma unroll
        for (int ks = 0; ks < 4; ks++) {
            uint32_t afr[4][4], bfr[4][2];
            #pragma unroll
            for (int mf = 0; mf < 4; mf++) {
                const uint32_t* p = (const uint32_t*)(sA + (ks * SBLK + ((wr * 4 + mf) * 32 + l) * 4) * 4);
                uint4 v = *(const uint4*)p;
                afr[mf][0] = v.x; afr[mf][1] = v.y; afr[mf][2] = v.z; afr[mf][3] = v.w;
            }
            #pragma unroll
            for (int nf = 0; nf < 4; nf++) {
                const uint32_t* p = (const uint32_t*)(sB + (ks * SBLK + ((wc * 4 + nf) * 32 + l) * 2) * 4);
                uint2 v = *(const uint2*)p;
                bfr[nf][0] = v.x; bfr[nf][1] = v.y;
            }
            #pragma unroll
            for (int mf = 0; mf < 4; mf++)
                #pragma unroll
                for (int nf = 0; nf < 4; nf++)
                    mma_tf32(acc[mf][nf], afr[mf], bfr[nf]);
        }
        store_tile(buf ^ 1);
        __syncthreads();
    }

    float* Cpart = (MODE == 0) ? g_part0 : g_part1;
    float* crow = Cpart + ((size_t)s * BATCH + m0 + wr * 64) * Ntot + n0 + wc * 32;
    #pragma unroll
    for (int mf = 0; mf < 4; mf++) {
        int mm = mf * 16 + (l >> 2);
        #pragma unroll
        for (int nf = 0; nf < 4; nf++) {
            int nn = nf * 8 + (l & 3) * 2;
            float2 v0 = make_float2(acc[mf][nf][0], acc[mf][nf][1]);
            float2 v1 = make_float2(acc[mf][nf][2], acc[mf][nf][3]);
            *(float2*)(crow + (size_t)mm * Ntot + nn) = v0;
            *(float2*)(crow + (size_t)(mm + 8) * Ntot + nn) = v1;
        }
    }
}

// ---------------- reductions / final ----------------
__global__ void __launch_bounds__(256) reduce0_kernel(const float* __restrict__ bias) {
    int f = blockIdx.x * 256 + threadIdx.x;   // float4 index, 262144 total
    const float4* p = (const float4*)g_part0;
    float4 b = ((const float4*)bias)[f & 255];
    float4 a0 = p[f], a1 = p[f + 262144], a2 = p[f + 2 * 262144], a3 = p[f + 3 * 262144];
    float4 o;
    o.x = fmaxf(a0.x + a1.x + a2.x + a3.x + b.x, 0.f);
    o.y = fmaxf(a0.y + a1.y + a2.y + a3.y + b.y, 0.f);
    o.z = fmaxf(a0.z + a1.z + a2.z + a3.z + b.z, 0.f);
    o.w = fmaxf(a0.w + a1.w + a2.w + a3.w + b.w, 0.f);
    ((float4*)g_h0)[f] = o;
}

__global__ void __launch_bounds__(256) reduce1_kernel(const float* __restrict__ bias) {
    int f = blockIdx.x * 256 + threadIdx.x;   // float4 index, 131072 total
    const float4* p = (const float4*)g_part1;
    float4 b = ((const float4*)bias)[f & 127];
    float4 a0 = p[f], a1 = p[f + 131072], a2 = p[f + 2 * 131072], a3 = p[f + 3 * 131072];
    float4 o;
    o.x = fmaxf(a0.x + a1.x + a2.x + a3.x + b.x, 0.f);
    o.y = fmaxf(a0.y + a1.y + a2.y + a3.y + b.y, 0.f);
    o.z = fmaxf(a0.z + a1.z + a2.z + a3.z + b.z, 0.f);
    o.w = fmaxf(a0.w + a1.w + a2.w + a3.w + b.w, 0.f);
    ((float4*)g_h1)[f] = o;
}

__global__ void __launch_bounds__(256) fc2_kernel(const float* __restrict__ w,
                                                  const float* __restrict__ bias,
                                                  float* __restrict__ out) {
    int wid = threadIdx.x >> 5, lane = threadIdx.x & 31;
    int row = blockIdx.x * 8 + wid;
    const float4* h = (const float4*)(g_h1 + (size_t)row * H2);
    const float4* wv = (const float4*)w;
    float s = 0.f;
    #pragma unroll
    for (int q = 0; q < 4; q++) {
        float4 a = h[lane + q * 32], b = wv[lane + q * 32];
        s += a.x * b.x + a.y * b.y + a.z * b.z + a.w * b.w;
    }
    #pragma unroll
    for (int o = 16; o; o >>= 1) s += __shfl_xor_sync(0xffffffffu, s, o);
    if (lane == 0) out[row] = 1.0f / (1.0f + expf(-(s + bias[0])));
}

// ---------------- launch ----------------
extern "C" void kernel_launch(void* const* d_in, const int* in_sizes, int n_in,
                              void* d_out, int out_size) {
    const float* x    = (const float*)d_in[0];
    const float* W1   = (const float*)d_in[1];
    const float* W2   = (const float*)d_in[2];
    const float* sw1  = (const float*)d_in[3];
    const float* sw2  = (const float*)d_in[4];
    const float* fc0w = (const float*)d_in[5];
    const float* fc0b = (const float*)d_in[6];
    const float* fc1w = (const float*)d_in[7];
    const float* fc1b = (const float*)d_in[8];
    const float* fc2w = (const float*)d_in[9];
    const float* fc2b = (const float*)d_in[10];
    float* out = (float*)d_out;

    cudaFuncSetAttribute(gemm_kernel<0>, cudaFuncAttributeMaxDynamicSharedMemorySize, SMEM_DYN);
    cudaFuncSetAttribute(gemm_kernel<1>, cudaFuncAttributeMaxDynamicSharedMemorySize, SMEM_DYN);

    init_pairs_kernel<<<1, 32>>>();
    se_kernel<<<BATCH, 256>>>(x, sw1, sw2);
    tfield_kernel<<<dim3(31, BATCH / 16, 2), 256>>>(x, W1, W2);
    gemm_kernel<0><<<8 * 8 * 4, 256, SMEM_DYN>>>(fc0w, x, H1, KTOT, 4);
    reduce0_kernel<<<1024, 256>>>(fc0b);
    gemm_kernel<1><<<8 * 4 * 4, 256, SMEM_DYN>>>(fc1w, nullptr, H2, H1, 4);
    reduce1_kernel<<<512, 256>>>(fc1b);
    fc2_kernel<<<BATCH / 8, 256>>>(fc2w, fc2b, out);
}

// round 4
// speedup vs baseline: 1.4344x; 1.4344x over previous
#include <cuda_runtime.h>
#include <cstdint>
#include <cstddef>

#define DI __device__ __forceinline__

#define BATCH 1024
#define NF    32
#define NPAIR 496
#define T_LD  1984
#define X_LD  2048
#define HALFK 31744
#define KTOT  63488
#define H1    1024
#define H2    512

// GEMM tile: BM=128, BN=128, BK=32, 256 threads (8 warps: 2 warp-rows x 4 warp-cols,
// warp tile 64x32). Row-major smem tiles with stride 36 floats (conflict-free).
#define SROW 36
#define TBUF 4608              // floats per tile buffer (128*36)
#define TBUF_BYTES (TBUF*4)    // 18432
#define SMEM_DYN (4*TBUF_BYTES) // 73728: [A0][B0][A1][B1]

__device__ float g_x2[BATCH*X_LD];
__device__ float g_T[2*BATCH*T_LD];
__device__ float g_part0[4*BATCH*H1];
__device__ float g_h0[BATCH*H1];
__device__ float g_part1[4*BATCH*H2];
__device__ float g_h1[BATCH*H2];
__device__ int   g_pi[NPAIR];
__device__ int   g_pj[NPAIR];

DI uint32_t f2tf(float x) {
    uint32_t r;
    asm("cvt.rna.tf32.f32 %0, %1;" : "=r"(r) : "f"(x));
    return r;
}

DI uint32_t smem_u32(const void* p) {
    uint32_t a;
    asm("{ .reg .u64 t; cvta.to.shared.u64 t, %1; cvt.u32.u64 %0, t; }" : "=r"(a) : "l"(p));
    return a;
}

DI void cp_async16(uint32_t dst, const void* src) {
    asm volatile("cp.async.cg.shared.global [%0], [%1], 16;" :: "r"(dst), "l"(src));
}
#define CP_COMMIT() asm volatile("cp.async.commit_group;" ::: "memory")
#define CP_WAIT0()  asm volatile("cp.async.wait_group 0;" ::: "memory")

DI void mma_tf32(float* d, const uint32_t* a, const uint32_t* b) {
    asm volatile(
        "mma.sync.aligned.m16n8k8.row.col.f32.tf32.tf32.f32 "
        "{%0,%1,%2,%3}, {%4,%5,%6,%7}, {%8,%9}, {%0,%1,%2,%3};"
        : "+f"(d[0]), "+f"(d[1]), "+f"(d[2]), "+f"(d[3])
        : "r"(a[0]), "r"(a[1]), "r"(a[2]), "r"(a[3]), "r"(b[0]), "r"(b[1]));
}

// ---------------- small kernels ----------------
__global__ void init_pairs_kernel() {
    if (threadIdx.x == 0) {
        int idx = 0;
        for (int i = 0; i < NF - 1; i++)
            for (int j = i + 1; j < NF; j++) { g_pi[idx] = i; g_pj[idx] = j; idx++; }
    }
}

__global__ void __launch_bounds__(256) se_kernel(const float* __restrict__ x,
                                                 const float* __restrict__ w1,
                                                 const float* __restrict__ w2) {
    __shared__ float xs[X_LD];
    __shared__ float Zs[NF], A1s[4], A2s[NF];
    int b = blockIdx.x, tid = threadIdx.x;
    const float4* xr = (const float4*)(x + (size_t)b * X_LD);
    float4* xs4 = (float4*)xs;
    xs4[tid] = xr[tid];
    xs4[tid + 256] = xr[tid + 256];
    __syncthreads();
    int wid = tid >> 5, lane = tid & 31;
    #pragma unroll
    for (int ff = 0; ff < 4; ff++) {
        int f = wid * 4 + ff;
        float v = xs[f * 64 + lane] + xs[f * 64 + 32 + lane];
        #pragma unroll
        for (int o = 16; o; o >>= 1) v += __shfl_xor_sync(0xffffffffu, v, o);
        if (lane == 0) Zs[f] = v * (1.0f / 64.0f);
    }
    __syncthreads();
    if (tid < 4) {
        float a = 0.f;
        #pragma unroll
        for (int f = 0; f < NF; f++) a += Zs[f] * w1[tid * NF + f];
        A1s[tid] = fmaxf(a, 0.0f);
    }
    __syncthreads();
    if (tid < NF) {
        float a = 0.f;
        #pragma unroll
        for (int r = 0; r < 4; r++) a += A1s[r] * w2[tid * 4 + r];
        A2s[tid] = 1.0f / (1.0f + expf(-a));
    }
    __syncthreads();
    float4* o4 = (float4*)(g_x2 + (size_t)b * X_LD);
    #pragma unroll
    for (int q = 0; q < 2; q++) {
        int i = tid + q * 256;
        float4 v = xs4[i];
        float sc = A2s[i >> 4];
        v.x *= sc; v.y *= sc; v.z *= sc; v.w *= sc;
        o4[i] = v;
    }
}

// t[v][b][i*64+o] = sum_e feats_v[b,i,e] * W_v[i,o,e]
__global__ void __launch_bounds__(256) tfield_kernel(const float* __restrict__ x,
                                                     const float* __restrict__ W1,
                                                     const float* __restrict__ W2) {
    __shared__ float Ws[64 * 68];
    __shared__ float xs[16 * 68];
    __shared__ float ts[1024];
    int v = blockIdx.z, fi = blockIdx.x, b0 = blockIdx.y * 16;
    int tid = threadIdx.x;
    const float* W = (v ? W2 : W1) + (size_t)fi * 4096;
    for (int idx = tid; idx < 4096; idx += 256)
        Ws[(idx >> 6) * 68 + (idx & 63)] = W[idx];
    const float* xsrc = (v ? g_x2 : x) + (size_t)b0 * X_LD + fi * 64;
    for (int idx = tid; idx < 1024; idx += 256)
        xs[(idx >> 6) * 68 + (idx & 63)] = xsrc[(size_t)(idx >> 6) * X_LD + (idx & 63)];
    __syncthreads();
    int o = tid >> 2, bg = tid & 3;
    float s0 = 0.f, s1 = 0.f, s2 = 0.f, s3 = 0.f;
    const float4* wrow = (const float4*)(Ws + o * 68);
    #pragma unroll
    for (int e4 = 0; e4 < 16; e4++) {
        float4 wv = wrow[e4];
        float4 a0 = *(const float4*)(xs + (bg * 4 + 0) * 68 + e4 * 4);
        float4 a1 = *(const float4*)(xs + (bg * 4 + 1) * 68 + e4 * 4);
        float4 a2 = *(const float4*)(xs + (bg * 4 + 2) * 68 + e4 * 4);
        float4 a3 = *(const float4*)(xs + (bg * 4 + 3) * 68 + e4 * 4);
        s0 += wv.x*a0.x + wv.y*a0.y + wv.z*a0.z + wv.w*a0.w;
        s1 += wv.x*a1.x + wv.y*a1.y + wv.z*a1.z + wv.w*a1.w;
        s2 += wv.x*a2.x + wv.y*a2.y + wv.z*a2.z + wv.w*a2.w;
        s3 += wv.x*a3.x + wv.y*a3.y + wv.z*a3.z + wv.w*a3.w;
    }
    ts[(bg * 4 + 0) * 64 + o] = s0;
    ts[(bg * 4 + 1) * 64 + o] = s1;
    ts[(bg * 4 + 2) * 64 + o] = s2;
    ts[(bg * 4 + 3) * 64 + o] = s3;
    __syncthreads();
    float* trow = g_T + (size_t)v * (BATCH * T_LD);
    for (int idx = tid; idx < 1024; idx += 256)
        trow[(size_t)(b0 + (idx >> 6)) * T_LD + fi * 64 + (idx & 63)] = ts[idx];
}

// ---------------- mma.sync tf32 GEMM ----------------
// C[m,n] = sum_k A[m,k] * W[n,k].
// MODE 0: A = on-the-fly bilinear feature tile (fc0; regs -> STS), C -> g_part0
// MODE 1: A = g_h0 via cp.async (fc1), C -> g_part1
// B always via cp.async (raw fp32 bits, HW-truncated tf32).
template<int MODE>
__global__ void __launch_bounds__(256, 2) gemm_kernel(const float* __restrict__ Bw,
                                                      const float* __restrict__ Xin,
                                                      int Ntot, int Ktot, int S) {
    extern __shared__ float sm[];
    uint32_t smb = smem_u32(sm);
    int tid = threadIdx.x;
    int w = tid >> 5, l = tid & 31;
    int wr = w >> 2, wc = w & 3;
    int nbn = Ntot >> 7;
    int s  = blockIdx.x % S;
    int nb = (blockIdx.x / S) % nbn;
    int mb = blockIdx.x / (S * nbn);
    int m0 = mb * 128, n0 = nb * 128;
    int Kper = Ktot / S;
    int k_base = s * Kper;
    int ntiles = Kper >> 5;

    int r0 = tid >> 3, c4 = tid & 7;   // per-thread chunk: rows r0, r0+32, r0+64, r0+96

    float acc[4][4][4];
    #pragma unroll
    for (int i = 0; i < 4; i++)
        #pragma unroll
        for (int j = 0; j < 4; j++)
            #pragma unroll
            for (int q = 0; q < 4; q++) acc[i][j][q] = 0.f;

    float4 av[4];

    auto load_A_regs = [&](int kg) {
        int half = (kg >= HALFK) ? 1 : 0;
        int rem = kg - half * HALFK;
        int p = rem >> 6, e0 = rem & 63;
        int ip = g_pi[p], jp = g_pj[p];
        const float* tb = g_T + (size_t)half * (BATCH * T_LD) + (size_t)m0 * T_LD + ip * 64 + e0 + c4 * 4;
        const float* xb = (half ? g_x2 : Xin) + (size_t)m0 * X_LD + jp * 64 + e0 + c4 * 4;
        #pragma unroll
        for (int it = 0; it < 4; it++) {
            int r = r0 + it * 32;
            float4 tv = *(const float4*)(tb + (size_t)r * T_LD);
            float4 xv = *(const float4*)(xb + (size_t)r * X_LD);
            av[it].x = tv.x * xv.x; av[it].y = tv.y * xv.y;
            av[it].z = tv.z * xv.z; av[it].w = tv.w * xv.w;
        }
    };
    auto store_A = [&](int buf) {
        float* sA = sm + buf * 2 * TBUF;
        #pragma unroll
        for (int it = 0; it < 4; it++) {
            int r = r0 + it * 32;
            uint4 bits;
            bits.x = f2tf(av[it].x); bits.y = f2tf(av[it].y);
            bits.z = f2tf(av[it].z); bits.w = f2tf(av[it].w);
            *(uint4*)(sA + r * SROW + c4 * 4) = bits;
        }
    };
    auto cp_A = [&](int kg, int buf) {   // MODE 1 only
        uint32_t dstb = smb + buf * 2 * TBUF_BYTES;
        const float* ab = g_h0 + (size_t)m0 * Ktot + kg + c4 * 4;
        #pragma unroll
        for (int it = 0; it < 4; it++) {
            int r = r0 + it * 32;
            cp_async16(dstb + (r * SROW + c4 * 4) * 4, ab + (size_t)r * Ktot);
        }
    };
    auto cp_B = [&](int kg, int buf) {
        uint32_t dstb = smb + (buf * 2 + 1) * TBUF_BYTES;
        const float* bb = Bw + (size_t)n0 * Ktot + kg + c4 * 4;
        #pragma unroll
        for (int it = 0; it < 4; it++) {
            int r = r0 + it * 32;
            cp_async16(dstb + (r * SROW + c4 * 4) * 4, bb + (size_t)r * Ktot);
        }
    };

    // prologue
    if (MODE == 0) { load_A_regs(k_base); }
    else          { cp_A(k_base, 0); }
    cp_B(k_base, 0);
    CP_COMMIT();
    if (MODE == 0) store_A(0);

    for (int kt = 0; kt < ntiles; kt++) {
        int buf = kt & 1;
        CP_WAIT0();
        __syncthreads();
        bool has_next = (kt + 1 < ntiles);
        if (has_next) {
            int kgn = k_base + ((kt + 1) << 5);
            if (MODE == 0) load_A_regs(kgn);
            else           cp_A(kgn, buf ^ 1);
            cp_B(kgn, buf ^ 1);
            CP_COMMIT();
        }
        const float* sA = sm + buf * 2 * TBUF;
        const float* sB = sA + TBUF;
        const uint32_t* uA = (const uint32_t*)sA;
        const uint32_t* uB = (const uint32_t*)sB;
        int mlane = l >> 2, klane = l & 3;
        #pragma unroll
        for (int ks = 0; ks < 4; ks++) {
            int kk = ks * 8 + klane;
            uint32_t afr[4][4], bfr[4][2];
            #pragma unroll
            for (int mf = 0; mf < 4; mf++) {
                int m = wr * 64 + mf * 16 + mlane;
                afr[mf][0] = uA[m * SROW + kk];
                afr[mf][1] = uA[(m + 8) * SROW + kk];
                afr[mf][2] = uA[m * SROW + kk + 4];
                afr[mf][3] = uA[(m + 8) * SROW + kk + 4];
            }
            #pragma unroll
            for (int nf = 0; nf < 4; nf++) {
                int n = wc * 32 + nf * 8 + mlane;
                bfr[nf][0] = uB[n * SROW + kk];
                bfr[nf][1] = uB[n * SROW + kk + 4];
            }
            #pragma unroll
            for (int mf = 0; mf < 4; mf++)
                #pragma unroll
                for (int nf = 0; nf < 4; nf++)
                    mma_tf32(acc[mf][nf], afr[mf], bfr[nf]);
        }
        if (has_next && MODE == 0) store_A(buf ^ 1);
    }

    float* Cpart = (MODE == 0) ? g_part0 : g_part1;
    float* crow = Cpart + ((size_t)s * BATCH + m0 + wr * 64) * Ntot + n0 + wc * 32;
    #pragma unroll
    for (int mf = 0; mf < 4; mf++) {
        int mm = mf * 16 + (l >> 2);
        #pragma unroll
        for (int nf = 0; nf < 4; nf++) {
            int nn = nf * 8 + (l & 3) * 2;
            *(float2*)(crow + (size_t)mm * Ntot + nn) = make_float2(acc[mf][nf][0], acc[mf][nf][1]);
            *(float2*)(crow + (size_t)(mm + 8) * Ntot + nn) = make_float2(acc[mf][nf][2], acc[mf][nf][3]);
        }
    }
}

// ---------------- reductions / final ----------------
__global__ void __launch_bounds__(256) reduce0_kernel(const float* __restrict__ bias) {
    int f = blockIdx.x * 256 + threadIdx.x;
    const float4* p = (const float4*)g_part0;
    float4 b = ((const float4*)bias)[f & 255];
    float4 a0 = p[f], a1 = p[f + 262144], a2 = p[f + 2 * 262144], a3 = p[f + 3 * 262144];
    float4 o;
    o.x = fmaxf(a0.x + a1.x + a2.x + a3.x + b.x, 0.f);
    o.y = fmaxf(a0.y + a1.y + a2.y + a3.y + b.y, 0.f);
    o.z = fmaxf(a0.z + a1.z + a2.z + a3.z + b.z, 0.f);
    o.w = fmaxf(a0.w + a1.w + a2.w + a3.w + b.w, 0.f);
    ((float4*)g_h0)[f] = o;
}

__global__ void __launch_bounds__(256) reduce1_kernel(const float* __restrict__ bias) {
    int f = blockIdx.x * 256 + threadIdx.x;
    const float4* p = (const float4*)g_part1;
    float4 b = ((const float4*)bias)[f & 127];
    float4 a0 = p[f], a1 = p[f + 131072], a2 = p[f + 2 * 131072], a3 = p[f + 3 * 131072];
    float4 o;
    o.x = fmaxf(a0.x + a1.x + a2.x + a3.x + b.x, 0.f);
    o.y = fmaxf(a0.y + a1.y + a2.y + a3.y + b.y, 0.f);
    o.z = fmaxf(a0.z + a1.z + a2.z + a3.z + b.z, 0.f);
    o.w = fmaxf(a0.w + a1.w + a2.w + a3.w + b.w, 0.f);
    ((float4*)g_h1)[f] = o;
}

__global__ void __launch_bounds__(256) fc2_kernel(const float* __restrict__ w,
                                                  const float* __restrict__ bias,
                                                  float* __restrict__ out) {
    int wid = threadIdx.x >> 5, lane = threadIdx.x & 31;
    int row = blockIdx.x * 8 + wid;
    const float4* h = (const float4*)(g_h1 + (size_t)row * H2);
    const float4* wv = (const float4*)w;
    float s = 0.f;
    #pragma unroll
    for (int q = 0; q < 4; q++) {
        float4 a = h[lane + q * 32], b = wv[lane + q * 32];
        s += a.x * b.x + a.y * b.y + a.z * b.z + a.w * b.w;
    }
    #pragma unroll
    for (int o = 16; o; o >>= 1) s += __shfl_xor_sync(0xffffffffu, s, o);
    if (lane == 0) out[row] = 1.0f / (1.0f + expf(-(s + bias[0])));
}

// ---------------- launch ----------------
extern "C" void kernel_launch(void* const* d_in, const int* in_sizes, int n_in,
                              void* d_out, int out_size) {
    const float* x    = (const float*)d_in[0];
    const float* W1   = (const float*)d_in[1];
    const float* W2   = (const float*)d_in[2];
    const float* sw1  = (const float*)d_in[3];
    const float* sw2  = (const float*)d_in[4];
    const float* fc0w = (const float*)d_in[5];
    const float* fc0b = (const float*)d_in[6];
    const float* fc1w = (const float*)d_in[7];
    const float* fc1b = (const float*)d_in[8];
    const float* fc2w = (const float*)d_in[9];
    const float* fc2b = (const float*)d_in[10];
    float* out = (float*)d_out;

    cudaFuncSetAttribute(gemm_kernel<0>, cudaFuncAttributeMaxDynamicSharedMemorySize, SMEM_DYN);
    cudaFuncSetAttribute(gemm_kernel<1>, cudaFuncAttributeMaxDynamicSharedMemorySize, SMEM_DYN);

    init_pairs_kernel<<<1, 32>>>();
    se_kernel<<<BATCH, 256>>>(x, sw1, sw2);
    tfield_kernel<<<dim3(31, BATCH / 16, 2), 256>>>(x, W1, W2);
    gemm_kernel<0><<<8 * 8 * 4, 256, SMEM_DYN>>>(fc0w, x, H1, KTOT, 4);
    reduce0_kernel<<<1024, 256>>>(fc0b);
    gemm_kernel<1><<<8 * 4 * 4, 256, SMEM_DYN>>>(fc1w, nullptr, H2, H1, 4);
    reduce1_kernel<<<512, 256>>>(fc1b);
    fc2_kernel<<<BATCH / 8, 256>>>(fc2w, fc2b, out);
}

// round 5
// speedup vs baseline: 2.1070x; 1.4689x over previous
#include <cuda_runtime.h>
#include <cuda_fp16.h>
#include <cstdint>
#include <cstddef>

#define DI __device__ __forceinline__

#define BATCH 1024
#define NF    32
#define NPAIR 496
#define T_LD  1984
#define X_LD  2048
#define HALFK 31744
#define KTOT  63488
#define H1    1024
#define H2    512

// GEMM tile: BM=128, BN=128, BK=32, 256 threads (8 warps: 2 warp-rows x 4 warp-cols,
// warp tile 64x32). fp16 operands in smem, row stride 40 halves (80B) -> conflict-free.
#define SROWH 40                 // halves per smem row
#define TBUFH_BYTES (128*SROWH*2) // 10240 bytes per tile buffer
#define SMEM_DYN (4*TBUFH_BYTES)  // 40960: [A0][B0][A1][B1]

__device__ float  g_x2[BATCH*X_LD];
__device__ float  g_T[2*BATCH*T_LD];
__device__ __half g_w0h[(size_t)H1*KTOT];   // fp16 fc0 weights (130MB)
__device__ __half g_w1h[H2*H1];
__device__ float  g_part0[4*BATCH*H1];
__device__ __half g_h0h[BATCH*H1];
__device__ float  g_part1[4*BATCH*H2];
__device__ float  g_h1[BATCH*H2];
__device__ int    g_pi[NPAIR];
__device__ int    g_pj[NPAIR];

DI uint32_t smem_u32(const void* p) {
    uint32_t a;
    asm("{ .reg .u64 t; cvta.to.shared.u64 t, %1; cvt.u32.u64 %0, t; }" : "=r"(a) : "l"(p));
    return a;
}

DI void cp_async16(uint32_t dst, const void* src) {
    asm volatile("cp.async.cg.shared.global [%0], [%1], 16;" :: "r"(dst), "l"(src));
}
#define CP_COMMIT() asm volatile("cp.async.commit_group;" ::: "memory")
#define CP_WAIT0()  asm volatile("cp.async.wait_group 0;" ::: "memory")

DI void mma_f16(float* d, const uint32_t* a, const uint32_t* b) {
    asm volatile(
        "mma.sync.aligned.m16n8k16.row.col.f32.f16.f16.f32 "
        "{%0,%1,%2,%3}, {%4,%5,%6,%7}, {%8,%9}, {%0,%1,%2,%3};"
        : "+f"(d[0]), "+f"(d[1]), "+f"(d[2]), "+f"(d[3])
        : "r"(a[0]), "r"(a[1]), "r"(a[2]), "r"(a[3]), "r"(b[0]), "r"(b[1]));
}

DI uint32_t pack_h2(float a, float b) {
    __half2 h = __floats2half2_rn(a, b);
    return *(uint32_t*)&h;
}

// ---------------- convert fp32 -> fp16 ----------------
__global__ void __launch_bounds__(256) f2h_kernel(const float* __restrict__ src,
                                                  __half* __restrict__ dst, int n4) {
    int i = blockIdx.x * 256 + threadIdx.x;
    if (i < n4) {
        float4 v = ((const float4*)src)[i];
        uint2 o;
        o.x = pack_h2(v.x, v.y);
        o.y = pack_h2(v.z, v.w);
        ((uint2*)dst)[i] = o;
    }
}

// ---------------- small kernels ----------------
__global__ void init_pairs_kernel() {
    if (threadIdx.x == 0) {
        int idx = 0;
        for (int i = 0; i < NF - 1; i++)
            for (int j = i + 1; j < NF; j++) { g_pi[idx] = i; g_pj[idx] = j; idx++; }
    }
}

__global__ void __launch_bounds__(256) se_kernel(const float* __restrict__ x,
                                                 const float* __restrict__ w1,
                                                 const float* __restrict__ w2) {
    __shared__ float xs[X_LD];
    __shared__ float Zs[NF], A1s[4], A2s[NF];
    int b = blockIdx.x, tid = threadIdx.x;
    const float4* xr = (const float4*)(x + (size_t)b * X_LD);
    float4* xs4 = (float4*)xs;
    xs4[tid] = xr[tid];
    xs4[tid + 256] = xr[tid + 256];
    __syncthreads();
    int wid = tid >> 5, lane = tid & 31;
    #pragma unroll
    for (int ff = 0; ff < 4; ff++) {
        int f = wid * 4 + ff;
        float v = xs[f * 64 + lane] + xs[f * 64 + 32 + lane];
        #pragma unroll
        for (int o = 16; o; o >>= 1) v += __shfl_xor_sync(0xffffffffu, v, o);
        if (lane == 0) Zs[f] = v * (1.0f / 64.0f);
    }
    __syncthreads();
    if (tid < 4) {
        float a = 0.f;
        #pragma unroll
        for (int f = 0; f < NF; f++) a += Zs[f] * w1[tid * NF + f];
        A1s[tid] = fmaxf(a, 0.0f);
    }
    __syncthreads();
    if (tid < NF) {
        float a = 0.f;
        #pragma unroll
        for (int r = 0; r < 4; r++) a += A1s[r] * w2[tid * 4 + r];
        A2s[tid] = 1.0f / (1.0f + expf(-a));
    }
    __syncthreads();
    float4* o4 = (float4*)(g_x2 + (size_t)b * X_LD);
    #pragma unroll
    for (int q = 0; q < 2; q++) {
        int i = tid + q * 256;
        float4 v = xs4[i];
        float sc = A2s[i >> 4];
        v.x *= sc; v.y *= sc; v.z *= sc; v.w *= sc;
        o4[i] = v;
    }
}

// t[v][b][i*64+o] = sum_e feats_v[b,i,e] * W_v[i,o,e]
__global__ void __launch_bounds__(256) tfield_kernel(const float* __restrict__ x,
                                                     const float* __restrict__ W1,
                                                     const float* __restrict__ W2) {
    __shared__ float Ws[64 * 68];
    __shared__ float xs[16 * 68];
    __shared__ float ts[1024];
    int v = blockIdx.z, fi = blockIdx.x, b0 = blockIdx.y * 16;
    int tid = threadIdx.x;
    const float* W = (v ? W2 : W1) + (size_t)fi * 4096;
    for (int idx = tid; idx < 4096; idx += 256)
        Ws[(idx >> 6) * 68 + (idx & 63)] = W[idx];
    const float* xsrc = (v ? g_x2 : x) + (size_t)b0 * X_LD + fi * 64;
    for (int idx = tid; idx < 1024; idx += 256)
        xs[(idx >> 6) * 68 + (idx & 63)] = xsrc[(size_t)(idx >> 6) * X_LD + (idx & 63)];
    __syncthreads();
    int o = tid >> 2, bg = tid & 3;
    float s0 = 0.f, s1 = 0.f, s2 = 0.f, s3 = 0.f;
    const float4* wrow = (const float4*)(Ws + o * 68);
    #pragma unroll
    for (int e4 = 0; e4 < 16; e4++) {
        float4 wv = wrow[e4];
        float4 a0 = *(const float4*)(xs + (bg * 4 + 0) * 68 + e4 * 4);
        float4 a1 = *(const float4*)(xs + (bg * 4 + 1) * 68 + e4 * 4);
        float4 a2 = *(const float4*)(xs + (bg * 4 + 2) * 68 + e4 * 4);
        float4 a3 = *(const float4*)(xs + (bg * 4 + 3) * 68 + e4 * 4);
        s0 += wv.x*a0.x + wv.y*a0.y + wv.z*a0.z + wv.w*a0.w;
        s1 += wv.x*a1.x + wv.y*a1.y + wv.z*a1.z + wv.w*a1.w;
        s2 += wv.x*a2.x + wv.y*a2.y + wv.z*a2.z + wv.w*a2.w;
        s3 += wv.x*a3.x + wv.y*a3.y + wv.z*a3.z + wv.w*a3.w;
    }
    ts[(bg * 4 + 0) * 64 + o] = s0;
    ts[(bg * 4 + 1) * 64 + o] = s1;
    ts[(bg * 4 + 2) * 64 + o] = s2;
    ts[(bg * 4 + 3) * 64 + o] = s3;
    __syncthreads();
    float* trow = g_T + (size_t)v * (BATCH * T_LD);
    for (int idx = tid; idx < 1024; idx += 256)
        trow[(size_t)(b0 + (idx >> 6)) * T_LD + fi * 64 + (idx & 63)] = ts[idx];
}

// ---------------- mma.sync fp16 GEMM ----------------
// C[m,n] = sum_k A[m,k] * W[n,k].
// MODE 0: A = on-the-fly bilinear feature tile (fp32 product -> half2 -> STS), C -> g_part0
// MODE 1: A = g_h0h via cp.async (fc1), C -> g_part1
// B always via cp.async from pre-converted fp16 weights.
template<int MODE>
__global__ void __launch_bounds__(256, 2) gemm_kernel(const __half* __restrict__ Bw,
                                                      const float* __restrict__ Xin,
                                                      int Ntot, int Ktot, int S) {
    extern __shared__ char smc[];
    uint32_t smb = smem_u32(smc);
    int tid = threadIdx.x;
    int w = tid >> 5, l = tid & 31;
    int wr = w >> 2, wc = w & 3;
    int nbn = Ntot >> 7;
    int s  = blockIdx.x % S;
    int nb = (blockIdx.x / S) % nbn;
    int mb = blockIdx.x / (S * nbn);
    int m0 = mb * 128, n0 = nb * 128;
    int Kper = Ktot / S;
    int k_base = s * Kper;
    int ntiles = Kper >> 5;

    int r0 = tid >> 3, c4 = tid & 7;         // MODE0 A-gen: rows r0+{0,32,64,96}, k chunk c4*4
    int cr = tid >> 2, cq = tid & 3;         // cp.async: rows cr,cr+64; 16B chunk cq

    float acc[4][4][4];
    #pragma unroll
    for (int i = 0; i < 4; i++)
        #pragma unroll
        for (int j = 0; j < 4; j++)
            #pragma unroll
            for (int q = 0; q < 4; q++) acc[i][j][q] = 0.f;

    uint32_t avh[8];  // 4 rows x 4 halves (2 half2 per row)

    auto load_A_regs = [&](int kg) {
        int half = (kg >= HALFK) ? 1 : 0;
        int rem = kg - half * HALFK;
        int p = rem >> 6, e0 = rem & 63;
        int ip = g_pi[p], jp = g_pj[p];
        const float* tb = g_T + (size_t)half * (BATCH * T_LD) + (size_t)m0 * T_LD + ip * 64 + e0 + c4 * 4;
        const float* xb = (half ? g_x2 : Xin) + (size_t)m0 * X_LD + jp * 64 + e0 + c4 * 4;
        #pragma unroll
        for (int it = 0; it < 4; it++) {
            int r = r0 + it * 32;
            float4 tv = *(const float4*)(tb + (size_t)r * T_LD);
            float4 xv = *(const float4*)(xb + (size_t)r * X_LD);
            avh[it * 2 + 0] = pack_h2(tv.x * xv.x, tv.y * xv.y);
            avh[it * 2 + 1] = pack_h2(tv.z * xv.z, tv.w * xv.w);
        }
    };
    auto store_A = [&](int buf) {
        uint32_t base = smb + buf * 2 * TBUFH_BYTES;
        #pragma unroll
        for (int it = 0; it < 4; it++) {
            int r = r0 + it * 32;
            uint32_t addr = base + r * (SROWH * 2) + c4 * 8;
            asm volatile("st.shared.v2.b32 [%0], {%1, %2};"
                         :: "r"(addr), "r"(avh[it * 2]), "r"(avh[it * 2 + 1]) : "memory");
        }
    };
    auto cp_A = [&](int kg, int buf) {   // MODE 1 only
        uint32_t base = smb + buf * 2 * TBUFH_BYTES;
        #pragma unroll
        for (int it = 0; it < 2; it++) {
            int r = cr + it * 64;
            cp_async16(base + r * (SROWH * 2) + cq * 16,
                       g_h0h + (size_t)(m0 + r) * Ktot + kg + cq * 8);
        }
    };
    auto cp_B = [&](int kg, int buf) {
        uint32_t base = smb + (buf * 2 + 1) * TBUFH_BYTES;
        #pragma unroll
        for (int it = 0; it < 2; it++) {
            int r = cr + it * 64;
            cp_async16(base + r * (SROWH * 2) + cq * 16,
                       Bw + (size_t)(n0 + r) * Ktot + kg + cq * 8);
        }
    };

    // prologue
    if (MODE == 0) load_A_regs(k_base); else cp_A(k_base, 0);
    cp_B(k_base, 0);
    CP_COMMIT();
    if (MODE == 0) store_A(0);

    int mlane = l >> 2, klane = l & 3;
    for (int kt = 0; kt < ntiles; kt++) {
        int buf = kt & 1;
        CP_WAIT0();
        __syncthreads();
        bool has_next = (kt + 1 < ntiles);
        if (has_next) {
            int kgn = k_base + ((kt + 1) << 5);
            if (MODE == 0) load_A_regs(kgn); else cp_A(kgn, buf ^ 1);
            cp_B(kgn, buf ^ 1);
            CP_COMMIT();
        }
        const uint32_t* uA = (const uint32_t*)(smc + buf * 2 * TBUFH_BYTES);
        const uint32_t* uB = (const uint32_t*)(smc + (buf * 2 + 1) * TBUFH_BYTES);
        #pragma unroll
        for (int ks = 0; ks < 2; ks++) {
            int kw = ks * 8 + klane;
            uint32_t afr[4][4], bfr[4][2];
            #pragma unroll
            for (int mf = 0; mf < 4; mf++) {
                int m = wr * 64 + mf * 16 + mlane;
                afr[mf][0] = uA[m * 20 + kw];
                afr[mf][1] = uA[(m + 8) * 20 + kw];
                afr[mf][2] = uA[m * 20 + kw + 4];
                afr[mf][3] = uA[(m + 8) * 20 + kw + 4];
            }
            #pragma unroll
            for (int nf = 0; nf < 4; nf++) {
                int n = wc * 32 + nf * 8 + mlane;
                bfr[nf][0] = uB[n * 20 + kw];
                bfr[nf][1] = uB[n * 20 + kw + 4];
            }
            #pragma unroll
            for (int mf = 0; mf < 4; mf++)
                #pragma unroll
                for (int nf = 0; nf < 4; nf++)
                    mma_f16(acc[mf][nf], afr[mf], bfr[nf]);
        }
        if (has_next && MODE == 0) store_A(buf ^ 1);
    }

    float* Cpart = (MODE == 0) ? g_part0 : g_part1;
    float* crow = Cpart + ((size_t)s * BATCH + m0 + wr * 64) * Ntot + n0 + wc * 32;
    #pragma unroll
    for (int mf = 0; mf < 4; mf++) {
        int mm = mf * 16 + (l >> 2);
        #pragma unroll
        for (int nf = 0; nf < 4; nf++) {
            int nn = nf * 8 + (l & 3) * 2;
            *(float2*)(crow + (size_t)mm * Ntot + nn) = make_float2(acc[mf][nf][0], acc[mf][nf][1]);
            *(float2*)(crow + (size_t)(mm + 8) * Ntot + nn) = make_float2(acc[mf][nf][2], acc[mf][nf][3]);
        }
    }
}

// ---------------- reductions / final ----------------
__global__ void __launch_bounds__(256) reduce0_kernel(const float* __restrict__ bias) {
    int f = blockIdx.x * 256 + threadIdx.x;   // float4 index, 262144 total
    const float4* p = (const float4*)g_part0;
    float4 b = ((const float4*)bias)[f & 255];
    float4 a0 = p[f], a1 = p[f + 262144], a2 = p[f + 2 * 262144], a3 = p[f + 3 * 262144];
    float rx = fmaxf(a0.x + a1.x + a2.x + a3.x + b.x, 0.f);
    float ry = fmaxf(a0.y + a1.y + a2.y + a3.y + b.y, 0.f);
    float rz = fmaxf(a0.z + a1.z + a2.z + a3.z + b.z, 0.f);
    float rw = fmaxf(a0.w + a1.w + a2.w + a3.w + b.w, 0.f);
    uint2 o;
    o.x = pack_h2(rx, ry);
    o.y = pack_h2(rz, rw);
    ((uint2*)g_h0h)[f] = o;
}

__global__ void __launch_bounds__(256) reduce1_kernel(const float* __restrict__ bias) {
    int f = blockIdx.x * 256 + threadIdx.x;   // float4 index, 131072 total
    const float4* p = (const float4*)g_part1;
    float4 b = ((const float4*)bias)[f & 127];
    float4 a0 = p[f], a1 = p[f + 131072], a2 = p[f + 2 * 131072], a3 = p[f + 3 * 131072];
    float4 o;
    o.x = fmaxf(a0.x + a1.x + a2.x + a3.x + b.x, 0.f);
    o.y = fmaxf(a0.y + a1.y + a2.y + a3.y + b.y, 0.f);
    o.z = fmaxf(a0.z + a1.z + a2.z + a3.z + b.z, 0.f);
    o.w = fmaxf(a0.w + a1.w + a2.w + a3.w + b.w, 0.f);
    ((float4*)g_h1)[f] = o;
}

__global__ void __launch_bounds__(256) fc2_kernel(const float* __restrict__ w,
                                                  const float* __restrict__ bias,
                                                  float* __restrict__ out) {
    int wid = threadIdx.x >> 5, lane = threadIdx.x & 31;
    int row = blockIdx.x * 8 + wid;
    const float4* h = (const float4*)(g_h1 + (size_t)row * H2);
    const float4* wv = (const float4*)w;
    float s = 0.f;
    #pragma unroll
    for (int q = 0; q < 4; q++) {
        float4 a = h[lane + q * 32], b = wv[lane + q * 32];
        s += a.x * b.x + a.y * b.y + a.z * b.z + a.w * b.w;
    }
    #pragma unroll
    for (int o = 16; o; o >>= 1) s += __shfl_xor_sync(0xffffffffu, s, o);
    if (lane == 0) out[row] = 1.0f / (1.0f + expf(-(s + bias[0])));
}

// ---------------- launch ----------------
extern "C" void kernel_launch(void* const* d_in, const int* in_sizes, int n_in,
                              void* d_out, int out_size) {
    const float* x    = (const float*)d_in[0];
    const float* W1   = (const float*)d_in[1];
    const float* W2   = (const float*)d_in[2];
    const float* sw1  = (const float*)d_in[3];
    const float* sw2  = (const float*)d_in[4];
    const float* fc0w = (const float*)d_in[5];
    const float* fc0b = (const float*)d_in[6];
    const float* fc1w = (const float*)d_in[7];
    const float* fc1b = (const float*)d_in[8];
    const float* fc2w = (const float*)d_in[9];
    const float* fc2b = (const float*)d_in[10];
    float* out = (float*)d_out;

    __half* w0h; cudaGetSymbolAddress((void**)&w0h, g_w0h);
    __half* w1h; cudaGetSymbolAddress((void**)&w1h, g_w1h);

    cudaFuncSetAttribute(gemm_kernel<0>, cudaFuncAttributeMaxDynamicSharedMemorySize, SMEM_DYN);
    cudaFuncSetAttribute(gemm_kernel<1>, cudaFuncAttributeMaxDynamicSharedMemorySize, SMEM_DYN);

    init_pairs_kernel<<<1, 32>>>();
    f2h_kernel<<<(H1 * (KTOT / 4) + 255) / 256, 256>>>(fc0w, w0h, H1 * (KTOT / 4));
    f2h_kernel<<<(H2 * (H1 / 4) + 255) / 256, 256>>>(fc1w, w1h, H2 * (H1 / 4));
    se_kernel<<<BATCH, 256>>>(x, sw1, sw2);
    tfield_kernel<<<dim3(31, BATCH / 16, 2), 256>>>(x, W1, W2);
    gemm_kernel<0><<<8 * 8 * 4, 256, SMEM_DYN>>>(w0h, x, H1, KTOT, 4);
    reduce0_kernel<<<1024, 256>>>(fc0b);
    gemm_kernel<1><<<8 * 4 * 4, 256, SMEM_DYN>>>(w1h, nullptr, H2, H1, 4);
    reduce1_kernel<<<512, 256>>>(fc1b);
    fc2_kernel<<<BATCH / 8, 256>>>(fc2w, fc2b, out);
}